// round 12
// baseline (speedup 1.0000x reference)
#include <cuda_runtime.h>
#include <math.h>

#define BB   64
#define TT   512
#define IND  256
#define HH   1024
#define OUTD 256

#define NCTA 64
#define COLS 16

// -------- device scratch --------
__device__ float g_xh[TT * BB * HH];      // [t][j][b]
__device__ float g_xz[TT * BB * HH];
__device__ float g_xr[TT * BB * HH];
__device__ float g_hP [2][HH * BB];       // h   fragment-packed, double-buffered
__device__ float g_hrP[2][HH * BB];       // h*r fragment-packed, double-buffered
__device__ float g_hT [HH * BB];          // plain [j][b], final step only
__device__ unsigned g_fh [NCTA];
__device__ unsigned g_fhr[NCTA];

// -------- helpers --------
__device__ __forceinline__ unsigned cvt_tf32(float x) {
    unsigned r; asm("cvt.rna.tf32.f32 %0, %1;" : "=r"(r) : "f"(x)); return r;
}
__device__ __forceinline__ void mma8(float (&d)[4], const unsigned (&a)[4], const unsigned (&b)[2]) {
    asm volatile("mma.sync.aligned.m16n8k8.row.col.f32.tf32.tf32.f32 "
                 "{%0,%1,%2,%3}, {%4,%5,%6,%7}, {%8,%9}, {%0,%1,%2,%3};"
                 : "+f"(d[0]), "+f"(d[1]), "+f"(d[2]), "+f"(d[3])
                 : "r"(a[0]), "r"(a[1]), "r"(a[2]), "r"(a[3]), "r"(b[0]), "r"(b[1]));
}
__device__ __forceinline__ float sigm_(float x) { return 1.0f / (1.0f + __expf(-x)); }

__device__ __forceinline__ unsigned long long splat2(float x) {
    unsigned long long r; asm("mov.b64 %0, {%1, %1};" : "=l"(r) : "f"(x)); return r;
}
__device__ __forceinline__ unsigned long long pack2(float x, float y) {
    unsigned long long r; asm("mov.b64 %0, {%1, %2};" : "=l"(r) : "f"(x), "f"(y)); return r;
}
__device__ __forceinline__ void fma2(unsigned long long& d, unsigned long long a, unsigned long long b) {
    asm("fma.rn.f32x2 %0, %1, %2, %0;" : "+l"(d) : "l"(a), "l"(b));
}
__device__ __forceinline__ float2 unpack2(unsigned long long v) {
    float2 f; asm("mov.b64 {%0, %1}, %2;" : "=f"(f.x), "=f"(f.y) : "l"(v)); return f;
}

// -------- dataflow sync --------
__device__ __forceinline__ void publish(unsigned* flag, unsigned val) {
    asm volatile("st.release.gpu.global.u32 [%0], %1;" :: "l"(flag), "r"(val) : "memory");
}
// Warp-collective wait on ALL 64 producer CTAs: each lane polls 2 flags.
__device__ __forceinline__ void waitAll(const unsigned* flags, unsigned target) {
    const unsigned* p = flags + (threadIdx.x & 31);
    unsigned v0, v1;
    do {
        asm volatile("ld.acquire.gpu.global.u32 %0, [%1];" : "=r"(v0) : "l"(p) : "memory");
        asm volatile("ld.acquire.gpu.global.u32 %0, [%1];" : "=r"(v1) : "l"(p + 32) : "memory");
    } while (!__all_sync(0xffffffffu,
                         ((int)(v0 - target) >= 0) && ((int)(v1 - target) >= 0)));
}

// -------- kernel 1: input projections --------
__global__ __launch_bounds__(256) void proj_kernel(
    const float* __restrict__ X,
    const float* __restrict__ W0, const float* __restrict__ W1, const float* __restrict__ W2,
    const float* __restrict__ b0, const float* __restrict__ b1, const float* __restrict__ b2)
{
    __shared__ float As[32][68];
    __shared__ float Bs[32][68];

    const int z = blockIdx.z;
    const float* W    = (z == 0) ? W0 : (z == 1) ? W1 : W2;
    const float* bias = (z == 0) ? b0 : (z == 1) ? b1 : b2;
    float*       outp = (z == 0) ? g_xh : (z == 1) ? g_xz : g_xr;

    const int t   = blockIdx.y;
    const int j0  = blockIdx.x * 64;
    const int tid = threadIdx.x;
    const int ty  = tid >> 4;
    const int tx  = tid & 15;

    unsigned long long acc2[4][2];
#pragma unroll
    for (int i = 0; i < 4; i++) { acc2[i][0] = 0ull; acc2[i][1] = 0ull; }

    for (int kt = 0; kt < IND; kt += 32) {
#pragma unroll
        for (int l = 0; l < 8; l++) {
            int flat = tid + l * 256;
            int row = flat >> 5, col = flat & 31;
            As[col][row] = W[(j0 + row) * IND + kt + col];
            Bs[col][row] = X[row * (TT * IND) + t * IND + kt + col];
        }
        __syncthreads();
#pragma unroll
        for (int kk = 0; kk < 32; kk++) {
            float4 a4 = *reinterpret_cast<const float4*>(&As[kk][ty * 4]);
            float4 b4 = *reinterpret_cast<const float4*>(&Bs[kk][tx * 4]);
            unsigned long long p01 = pack2(b4.x, b4.y);
            unsigned long long p23 = pack2(b4.z, b4.w);
            float a[4] = { a4.x, a4.y, a4.z, a4.w };
#pragma unroll
            for (int i = 0; i < 4; i++) {
                unsigned long long aa = splat2(a[i]);
                fma2(acc2[i][0], aa, p01);
                fma2(acc2[i][1], aa, p23);
            }
        }
        __syncthreads();
    }
#pragma unroll
    for (int i = 0; i < 4; i++) {
        int j = j0 + ty * 4 + i;
        float bvv = bias[j];
        float2 p0 = unpack2(acc2[i][0]);
        float2 p1 = unpack2(acc2[i][1]);
        float4 v = make_float4(p0.x + bvv, p0.y + bvv, p1.x + bvv, p1.y + bvv);
        *reinterpret_cast<float4*>(&outp[t * (HH * BB) + j * BB + tx * 4]) = v;
    }
}

// -------- kernel 2: persistent scan --------
// 64 CTAs x 256 thr (8 warps). Warp w: batch-group bm=w&3 (16 rows), col-octet
// cn=w>>2 (8 cols), FULL K=1024 -> complete m16n8 tile, no cross-warp reduction.
// Pointwise state (h, z) persists in the tile-owner thread's registers.
__global__ __launch_bounds__(256, 1) void scan_kernel(
    const float* __restrict__ Wh, const float* __restrict__ Vz, const float* __restrict__ Vr)
{
    extern __shared__ float smem[];
    float* Bp = smem;   // 3*128*2*64 = 49152 floats (tf32 weight frags)

    const int tid  = threadIdx.x;
    const int w    = tid >> 5;
    const int lane = tid & 31;
    const int q    = lane >> 2;
    const int c    = lane & 3;
    const int bm   = w & 3;
    const int cn   = w >> 2;
    const int j0   = blockIdx.x * COLS;

    const unsigned F0h  = g_fh [blockIdx.x];
    const unsigned F0hr = g_fhr[blockIdx.x];

    // weight fragments -> smem (identical packing to R6, verified)
    {
        const float* srcs[3] = { Wh, Vz, Vr };
        for (int g = 0; g < 3; g++) {
            const float* S = srcs[g];
            for (int idx = tid; idx < COLS * HH; idx += 256) {
                int j = idx >> 10, k = idx & 1023;
                float v = S[(j0 + j) * HH + k];
                Bp[(((g * 128 + (k >> 3)) * 2 + (j >> 3)) * 64)
                   + ((j & 7) * 4 + (k & 3)) * 2 + ((k >> 2) & 1)]
                    = __uint_as_float(cvt_tf32(v));
            }
        }
    }

    // Per-thread owned elements (D-frag of the m16n8 tile):
    //   i: s=i>>1 (row q+8s), dd=i&1 (col 2c+dd)
    int paddr[4], xoff[4];
#pragma unroll
    for (int i = 0; i < 4; i++) {
        int s_ = i >> 1, dd = i & 1;
        int b  = bm * 16 + q + 8 * s_;
        int jl = cn * 8 + 2 * c + dd;
        int kg = blockIdx.x * 2 + cn;
        int k7 = 2 * c + dd;
        paddr[i] = (kg * 4 + bm) * 128 + (q * 4 + (k7 & 3)) * 4 + s_ + 2 * (k7 >> 2);
        xoff[i]  = (j0 + jl) * BB + b;
    }

    float hst[4] = {0, 0, 0, 0}, zst[4] = {0, 0, 0, 0};

    // hr@-1 = 0 into buffer 1 (256 thr x 4 = full CTA slice), publish
#pragma unroll
    for (int i = 0; i < 4; i++) __stcg(&g_hrP[1][paddr[i]], 0.0f);
    __syncthreads();
    if (tid == 0) publish(&g_fhr[blockIdx.x], F0hr + 1);

    for (int t = 0; t < TT; t++) {
        // prefetch pointwise inputs (independent; hidden behind flag wait)
        float xh[4], xz[4], xr[4];
#pragma unroll
        for (int i = 0; i < 4; i++) {
            int o = t * (HH * BB) + xoff[i];
            xh[i] = g_xh[o]; xz[i] = g_xz[o]; xr[i] = g_xr[o];
        }

        // ---------- phase 1: (h*r) @ Wh^T (full K, 4 rotating accumulators) ----
        waitAll(g_fhr, F0hr + 1 + t);
        const float4* hrb = (const float4*)g_hrP[(t + 1) & 1];

        float acc[4][4];
#pragma unroll
        for (int a = 0; a < 4; a++)
#pragma unroll
            for (int r = 0; r < 4; r++) acc[a][r] = 0.f;

#pragma unroll 8
        for (int ki = 0; ki < 128; ki++) {
            float4 av = __ldcg(&hrb[(ki * 4 + bm) * 32 + lane]);
            unsigned af[4] = { __float_as_uint(av.x), __float_as_uint(av.y),
                               __float_as_uint(av.z), __float_as_uint(av.w) };
            float2 bf = *(const float2*)&Bp[(ki * 2 + cn) * 64 + lane * 2];
            unsigned bq[2] = { __float_as_uint(bf.x), __float_as_uint(bf.y) };
            mma8(acc[ki & 3], af, bq);
        }
        {
            float* hbuf = g_hP[t & 1];
#pragma unroll
            for (int i = 0; i < 4; i++) {
                float s = (acc[0][i] + acc[1][i]) + (acc[2][i] + acc[3][i]);
                float ht = tanhf(xh[i] + s);
                hst[i] = zst[i] * hst[i] + (1.f - zst[i]) * ht;
                __stcg(&hbuf[paddr[i]], __uint_as_float(cvt_tf32(hst[i])));
            }
            if (t == TT - 1) {
#pragma unroll
                for (int i = 0; i < 4; i++) g_hT[xoff[i]] = hst[i];
            }
        }
        __syncthreads();
        if (tid == 0) publish(&g_fh[blockIdx.x], F0h + 1 + t);

        // ---------- phase 2: h @ Vz^T and h @ Vr^T (A loaded once) -------------
        waitAll(g_fh, F0h + 1 + t);
        const float4* hbc = (const float4*)g_hP[t & 1];

        float az[2][4], ar[2][4];
#pragma unroll
        for (int a = 0; a < 2; a++)
#pragma unroll
            for (int r = 0; r < 4; r++) { az[a][r] = 0.f; ar[a][r] = 0.f; }

#pragma unroll 4
        for (int ki = 0; ki < 128; ki++) {
            float4 av = __ldcg(&hbc[(ki * 4 + bm) * 32 + lane]);
            unsigned af[4] = { __float_as_uint(av.x), __float_as_uint(av.y),
                               __float_as_uint(av.z), __float_as_uint(av.w) };
            float2 zf = *(const float2*)&Bp[((128 + ki) * 2 + cn) * 64 + lane * 2];
            float2 rf = *(const float2*)&Bp[((256 + ki) * 2 + cn) * 64 + lane * 2];
            unsigned bz[2] = { __float_as_uint(zf.x), __float_as_uint(zf.y) };
            unsigned br[2] = { __float_as_uint(rf.x), __float_as_uint(rf.y) };
            mma8(az[ki & 1], af, bz);
            mma8(ar[ki & 1], af, br);
        }
        {
            float* hrw = g_hrP[t & 1];
#pragma unroll
            for (int i = 0; i < 4; i++) {
                float sz = az[0][i] + az[1][i];
                float sr = ar[0][i] + ar[1][i];
                zst[i] = sigm_(xz[i] + sz);
                float ri = sigm_(xr[i] + sr);
                __stcg(&hrw[paddr[i]], __uint_as_float(cvt_tf32(hst[i] * ri)));
            }
        }
        __syncthreads();
        if (tid == 0) publish(&g_fhr[blockIdx.x], F0hr + 2 + t);
    }
}

// -------- kernel 3: output projection --------
__global__ __launch_bounds__(256) void out_kernel(
    const float* __restrict__ Wo, const float* __restrict__ bo, float* __restrict__ out)
{
    const int b = threadIdx.x & 63;
    const int o = blockIdx.x * 4 + (threadIdx.x >> 6);
    float s = 0.f;
#pragma unroll 8
    for (int j = 0; j < HH; j++)
        s += g_hT[j * BB + b] * Wo[o * HH + j];
    out[b * OUTD + o] = s + bo[o];
}

extern "C" void kernel_launch(void* const* d_in, const int* in_sizes, int n_in,
                              void* d_out, int out_size) {
    const float* X  = (const float*)d_in[0];
    const float* Wx = (const float*)d_in[1];
    const float* bx = (const float*)d_in[2];
    const float* Wh = (const float*)d_in[3];
    const float* Uz = (const float*)d_in[4];
    const float* bz = (const float*)d_in[5];
    const float* Vz = (const float*)d_in[6];
    const float* Ur = (const float*)d_in[7];
    const float* br = (const float*)d_in[8];
    const float* Vr = (const float*)d_in[9];
    const float* Wo = (const float*)d_in[10];
    const float* bo = (const float*)d_in[11];
    float* out = (float*)d_out;

    const int scan_smem = 49152 * (int)sizeof(float);
    cudaFuncSetAttribute(scan_kernel, cudaFuncAttributeMaxDynamicSharedMemorySize, scan_smem);

    dim3 pg(HH / 64, TT, 3);
    proj_kernel<<<pg, 256>>>(X, Wx, Uz, Ur, bx, bz, br);
    scan_kernel<<<NCTA, 256, scan_smem>>>(Wh, Vz, Vr);
    out_kernel<<<OUTD / 4, 256>>>(Wo, bo, out);
}

// round 13
// speedup vs baseline: 1.2898x; 1.2898x over previous
#include <cuda_runtime.h>
#include <math.h>

#define BB   64
#define TT   512
#define IND  256
#define HH   1024
#define OUTD 256

#define NCTA 64
#define COLS 16

// -------- device scratch --------
__device__ float g_xh[TT * BB * HH];      // [t][j][b]
__device__ float g_xz[TT * BB * HH];
__device__ float g_xr[TT * BB * HH];
__device__ float g_hP [2][HH * BB];       // h   fragment-packed, double-buffered
__device__ float g_hrP[2][HH * BB];       // h*r fragment-packed, double-buffered
__device__ float g_hT [HH * BB];          // plain [j][b], final step only
__device__ unsigned g_fh [NCTA];
__device__ unsigned g_fhr[NCTA];

// -------- helpers --------
__device__ __forceinline__ unsigned cvt_tf32(float x) {
    unsigned r; asm("cvt.rna.tf32.f32 %0, %1;" : "=r"(r) : "f"(x)); return r;
}
__device__ __forceinline__ void mma8(float (&d)[4], const unsigned (&a)[4], const unsigned (&b)[2]) {
    asm volatile("mma.sync.aligned.m16n8k8.row.col.f32.tf32.tf32.f32 "
                 "{%0,%1,%2,%3}, {%4,%5,%6,%7}, {%8,%9}, {%0,%1,%2,%3};"
                 : "+f"(d[0]), "+f"(d[1]), "+f"(d[2]), "+f"(d[3])
                 : "r"(a[0]), "r"(a[1]), "r"(a[2]), "r"(a[3]), "r"(b[0]), "r"(b[1]));
}
__device__ __forceinline__ float sigm_(float x) { return 1.0f / (1.0f + __expf(-x)); }

__device__ __forceinline__ unsigned long long splat2(float x) {
    unsigned long long r; asm("mov.b64 %0, {%1, %1};" : "=l"(r) : "f"(x)); return r;
}
__device__ __forceinline__ unsigned long long pack2(float x, float y) {
    unsigned long long r; asm("mov.b64 %0, {%1, %2};" : "=l"(r) : "f"(x), "f"(y)); return r;
}
__device__ __forceinline__ void fma2(unsigned long long& d, unsigned long long a, unsigned long long b) {
    asm("fma.rn.f32x2 %0, %1, %2, %0;" : "+l"(d) : "l"(a), "l"(b));
}
__device__ __forceinline__ float2 unpack2(unsigned long long v) {
    float2 f; asm("mov.b64 {%0, %1}, %2;" : "=f"(f.x), "=f"(f.y) : "l"(v)); return f;
}

// -------- dataflow sync --------
__device__ __forceinline__ void publish(unsigned* flag, unsigned val) {
    asm volatile("st.release.gpu.global.u32 [%0], %1;" :: "l"(flag), "r"(val) : "memory");
}
// Warp-collective wait on 32 producer CTAs (one flag per lane).
__device__ __forceinline__ void wait32(const unsigned* flags, int base, unsigned target) {
    const unsigned* p = flags + base + (threadIdx.x & 31);
    unsigned v;
    do {
        asm volatile("ld.acquire.gpu.global.u32 %0, [%1];" : "=r"(v) : "l"(p) : "memory");
    } while (!__all_sync(0xffffffffu, (int)(v - target) >= 0));
}

// -------- kernel 1: input projections --------
__global__ __launch_bounds__(256) void proj_kernel(
    const float* __restrict__ X,
    const float* __restrict__ W0, const float* __restrict__ W1, const float* __restrict__ W2,
    const float* __restrict__ b0, const float* __restrict__ b1, const float* __restrict__ b2)
{
    __shared__ float As[32][68];
    __shared__ float Bs[32][68];

    const int z = blockIdx.z;
    const float* W    = (z == 0) ? W0 : (z == 1) ? W1 : W2;
    const float* bias = (z == 0) ? b0 : (z == 1) ? b1 : b2;
    float*       outp = (z == 0) ? g_xh : (z == 1) ? g_xz : g_xr;

    const int t   = blockIdx.y;
    const int j0  = blockIdx.x * 64;
    const int tid = threadIdx.x;
    const int ty  = tid >> 4;
    const int tx  = tid & 15;

    unsigned long long acc2[4][2];
#pragma unroll
    for (int i = 0; i < 4; i++) { acc2[i][0] = 0ull; acc2[i][1] = 0ull; }

    for (int kt = 0; kt < IND; kt += 32) {
#pragma unroll
        for (int l = 0; l < 8; l++) {
            int flat = tid + l * 256;
            int row = flat >> 5, col = flat & 31;
            As[col][row] = W[(j0 + row) * IND + kt + col];
            Bs[col][row] = X[row * (TT * IND) + t * IND + kt + col];
        }
        __syncthreads();
#pragma unroll
        for (int kk = 0; kk < 32; kk++) {
            float4 a4 = *reinterpret_cast<const float4*>(&As[kk][ty * 4]);
            float4 b4 = *reinterpret_cast<const float4*>(&Bs[kk][tx * 4]);
            unsigned long long p01 = pack2(b4.x, b4.y);
            unsigned long long p23 = pack2(b4.z, b4.w);
            float a[4] = { a4.x, a4.y, a4.z, a4.w };
#pragma unroll
            for (int i = 0; i < 4; i++) {
                unsigned long long aa = splat2(a[i]);
                fma2(acc2[i][0], aa, p01);
                fma2(acc2[i][1], aa, p23);
            }
        }
        __syncthreads();
    }
#pragma unroll
    for (int i = 0; i < 4; i++) {
        int j = j0 + ty * 4 + i;
        float bvv = bias[j];
        float2 p0 = unpack2(acc2[i][0]);
        float2 p1 = unpack2(acc2[i][1]);
        float4 v = make_float4(p0.x + bvv, p0.y + bvv, p1.x + bvv, p1.y + bvv);
        *reinterpret_cast<float4*>(&outp[t * (HH * BB) + j * BB + tx * 4]) = v;
    }
}

// -------- kernel 2: persistent scan --------
// 8 warps: kh=w>>2 (K-half of 512), bm=w&3 (batch quad m16). Warp computes
// m16 x n16 (all CTA cols) over its K-half. kh=0 warps own outputs + state;
// kh=1 warps contribute one smem partial (STS.64 pairs). tf32 mma, fp32 acc.
__global__ __launch_bounds__(256, 1) void scan_kernel(
    const float* __restrict__ Wh, const float* __restrict__ Vz, const float* __restrict__ Vr)
{
    extern __shared__ float smem[];
    float* Bp   = smem;                 // 49152 floats (tf32 weight frags)
    float* redh = smem + 49152;         // 4*288
    float* redz = smem + 50304;         // 4*288
    float* redr = smem + 51456;         // 4*288

    const int tid  = threadIdx.x;
    const int w    = tid >> 5;
    const int lane = tid & 31;
    const int q    = lane >> 2;
    const int c    = lane & 3;
    const int kh   = w >> 2;
    const int bm   = w & 3;
    const int kh64 = kh * 64;
    const int j0   = blockIdx.x * COLS;
    const bool owner = (kh == 0);

    const unsigned F0h  = g_fh [blockIdx.x];
    const unsigned F0hr = g_fhr[blockIdx.x];

    // weight fragments -> smem (R10-verified packing)
    {
        const float* srcs[3] = { Wh, Vz, Vr };
        for (int g = 0; g < 3; g++) {
            const float* S = srcs[g];
            for (int idx = tid; idx < COLS * HH; idx += 256) {
                int j = idx >> 10, k = idx & 1023;
                float v = S[(j0 + j) * HH + k];
                Bp[(((g * 128 + (k >> 3)) * 2 + (j >> 3)) * 64)
                   + ((j & 7) * 4 + (k & 3)) * 2 + ((k >> 2) & 1)]
                    = __uint_as_float(cvt_tf32(v));
            }
        }
    }

    // 8 owned elements per owner thread: e = nt*4 + p*2 + dd
    int paddr[8], xoff[8];
#pragma unroll
    for (int nt = 0; nt < 2; nt++)
#pragma unroll
        for (int p = 0; p < 2; p++)
#pragma unroll
            for (int dd = 0; dd < 2; dd++) {
                int e  = nt * 4 + p * 2 + dd;
                int b  = bm * 16 + q + 8 * p;
                int jl = nt * 8 + 2 * c + dd;
                int k7 = 2 * c + dd;
                int ksg = blockIdx.x * 2 + nt;    // global (j0+jl)>>3
                paddr[e] = (ksg * 4 + bm) * 128 + (q * 4 + (k7 & 3)) * 4 + p + 2 * (k7 >> 2);
                xoff[e]  = (j0 + jl) * BB + b;
            }

    float hst[8], zst[8];
#pragma unroll
    for (int e = 0; e < 8; e++) { hst[e] = 0.f; zst[e] = 0.f; }

    // hr@-1 = 0 into buffer 1 (owners cover the full CTA slice), publish
    if (owner) {
#pragma unroll
        for (int e = 0; e < 8; e++) __stcg(&g_hrP[1][paddr[e]], 0.0f);
    }
    __syncthreads();
    if (tid == 0) publish(&g_fhr[blockIdx.x], F0hr + 1);

    for (int t = 0; t < TT; t++) {
        // pointwise inputs (owners), issued before the wait
        float xh[8], xz[8], xr[8];
        if (owner) {
#pragma unroll
            for (int e = 0; e < 8; e++) {
                int o = t * (HH * BB) + xoff[e];
                xh[e] = g_xh[o]; xz[e] = g_xz[o]; xr[e] = g_xr[o];
            }
        }

        // ---------- phase 1: (h*r) @ Wh^T ----------
        wait32(g_fhr, kh * 32, F0hr + 1 + t);
        const float4* hrb = (const float4*)g_hrP[(t + 1) & 1];

        float acc[2][4][4];
#pragma unroll
        for (int n = 0; n < 2; n++)
#pragma unroll
            for (int a = 0; a < 4; a++)
#pragma unroll
                for (int r = 0; r < 4; r++) acc[n][a][r] = 0.f;

#pragma unroll 8
        for (int it = 0; it < 64; it++) {
            int ksg = kh64 + it;
            float4 av = __ldcg(&hrb[(ksg * 4 + bm) * 32 + lane]);
            unsigned af[4] = { __float_as_uint(av.x), __float_as_uint(av.y),
                               __float_as_uint(av.z), __float_as_uint(av.w) };
            float2 f0 = *(const float2*)&Bp[(ksg * 2 + 0) * 64 + lane * 2];
            float2 f1 = *(const float2*)&Bp[(ksg * 2 + 1) * 64 + lane * 2];
            unsigned bq0[2] = { __float_as_uint(f0.x), __float_as_uint(f0.y) };
            unsigned bq1[2] = { __float_as_uint(f1.x), __float_as_uint(f1.y) };
            mma8(acc[0][it & 3], af, bq0);
            mma8(acc[1][it & 3], af, bq1);
        }
        float s1[2][4];
#pragma unroll
        for (int n = 0; n < 2; n++)
#pragma unroll
            for (int r = 0; r < 4; r++)
                s1[n][r] = (acc[n][0][r] + acc[n][1][r]) + (acc[n][2][r] + acc[n][3][r]);

        if (!owner) {
#pragma unroll
            for (int n = 0; n < 2; n++)
#pragma unroll
                for (int p = 0; p < 2; p++)
                    *(float2*)&redh[bm * 288 + (q + 8 * p) * 18 + n * 8 + 2 * c]
                        = make_float2(s1[n][2 * p], s1[n][2 * p + 1]);
        }
        __syncthreads();
        if (owner) {
            float* hbuf = g_hP[t & 1];
#pragma unroll
            for (int n = 0; n < 2; n++)
#pragma unroll
                for (int p = 0; p < 2; p++) {
                    float2 pr = *(const float2*)&redh[bm * 288 + (q + 8 * p) * 18 + n * 8 + 2 * c];
                    float sv[2] = { s1[n][2 * p] + pr.x, s1[n][2 * p + 1] + pr.y };
#pragma unroll
                    for (int dd = 0; dd < 2; dd++) {
                        int e = n * 4 + p * 2 + dd;
                        float ht = tanhf(xh[e] + sv[dd]);
                        hst[e] = zst[e] * hst[e] + (1.f - zst[e]) * ht;
                        __stcg(&hbuf[paddr[e]], __uint_as_float(cvt_tf32(hst[e])));
                    }
                }
            if (t == TT - 1) {
#pragma unroll
                for (int e = 0; e < 8; e++) g_hT[xoff[e]] = hst[e];
            }
        }
        __syncthreads();
        if (tid == 0) publish(&g_fh[blockIdx.x], F0h + 1 + t);

        // ---------- phase 2: h @ Vz^T and h @ Vr^T ----------
        wait32(g_fh, kh * 32, F0h + 1 + t);
        const float4* hbc = (const float4*)g_hP[t & 1];

        float az[2][2][4], ar[2][2][4];
#pragma unroll
        for (int n = 0; n < 2; n++)
#pragma unroll
            for (int a = 0; a < 2; a++)
#pragma unroll
                for (int r = 0; r < 4; r++) { az[n][a][r] = 0.f; ar[n][a][r] = 0.f; }

#pragma unroll 8
        for (int it = 0; it < 64; it++) {
            int ksg = kh64 + it;
            float4 av = __ldcg(&hbc[(ksg * 4 + bm) * 32 + lane]);
            unsigned af[4] = { __float_as_uint(av.x), __float_as_uint(av.y),
                               __float_as_uint(av.z), __float_as_uint(av.w) };
            float2 zf0 = *(const float2*)&Bp[((128 + ksg) * 2 + 0) * 64 + lane * 2];
            float2 zf1 = *(const float2*)&Bp[((128 + ksg) * 2 + 1) * 64 + lane * 2];
            float2 rf0 = *(const float2*)&Bp[((256 + ksg) * 2 + 0) * 64 + lane * 2];
            float2 rf1 = *(const float2*)&Bp[((256 + ksg) * 2 + 1) * 64 + lane * 2];
            unsigned bz0[2] = { __float_as_uint(zf0.x), __float_as_uint(zf0.y) };
            unsigned bz1[2] = { __float_as_uint(zf1.x), __float_as_uint(zf1.y) };
            unsigned br0[2] = { __float_as_uint(rf0.x), __float_as_uint(rf0.y) };
            unsigned br1[2] = { __float_as_uint(rf1.x), __float_as_uint(rf1.y) };
            mma8(az[0][it & 1], af, bz0);
            mma8(az[1][it & 1], af, bz1);
            mma8(ar[0][it & 1], af, br0);
            mma8(ar[1][it & 1], af, br1);
        }
        float sz1[2][4], sr1[2][4];
#pragma unroll
        for (int n = 0; n < 2; n++)
#pragma unroll
            for (int r = 0; r < 4; r++) {
                sz1[n][r] = az[n][0][r] + az[n][1][r];
                sr1[n][r] = ar[n][0][r] + ar[n][1][r];
            }

        if (!owner) {
#pragma unroll
            for (int n = 0; n < 2; n++)
#pragma unroll
                for (int p = 0; p < 2; p++) {
                    int ad = bm * 288 + (q + 8 * p) * 18 + n * 8 + 2 * c;
                    *(float2*)&redz[ad] = make_float2(sz1[n][2 * p], sz1[n][2 * p + 1]);
                    *(float2*)&redr[ad] = make_float2(sr1[n][2 * p], sr1[n][2 * p + 1]);
                }
        }
        __syncthreads();
        if (owner) {
            float* hrw = g_hrP[t & 1];
#pragma unroll
            for (int n = 0; n < 2; n++)
#pragma unroll
                for (int p = 0; p < 2; p++) {
                    int ad = bm * 288 + (q + 8 * p) * 18 + n * 8 + 2 * c;
                    float2 pz = *(const float2*)&redz[ad];
                    float2 prr = *(const float2*)&redr[ad];
                    float svz[2] = { sz1[n][2 * p] + pz.x, sz1[n][2 * p + 1] + pz.y };
                    float svr[2] = { sr1[n][2 * p] + prr.x, sr1[n][2 * p + 1] + prr.y };
#pragma unroll
                    for (int dd = 0; dd < 2; dd++) {
                        int e = n * 4 + p * 2 + dd;
                        zst[e] = sigm_(xz[e] + svz[dd]);
                        float ri = sigm_(xr[e] + svr[dd]);
                        __stcg(&hrw[paddr[e]], __uint_as_float(cvt_tf32(hst[e] * ri)));
                    }
                }
        }
        __syncthreads();
        if (tid == 0) publish(&g_fhr[blockIdx.x], F0hr + 2 + t);
    }
}

// -------- kernel 3: output projection --------
__global__ __launch_bounds__(256) void out_kernel(
    const float* __restrict__ Wo, const float* __restrict__ bo, float* __restrict__ out)
{
    const int b = threadIdx.x & 63;
    const int o = blockIdx.x * 4 + (threadIdx.x >> 6);
    float s = 0.f;
#pragma unroll 8
    for (int j = 0; j < HH; j++)
        s += g_hT[j * BB + b] * Wo[o * HH + j];
    out[b * OUTD + o] = s + bo[o];
}

extern "C" void kernel_launch(void* const* d_in, const int* in_sizes, int n_in,
                              void* d_out, int out_size) {
    const float* X  = (const float*)d_in[0];
    const float* Wx = (const float*)d_in[1];
    const float* bx = (const float*)d_in[2];
    const float* Wh = (const float*)d_in[3];
    const float* Uz = (const float*)d_in[4];
    const float* bz = (const float*)d_in[5];
    const float* Vz = (const float*)d_in[6];
    const float* Ur = (const float*)d_in[7];
    const float* br = (const float*)d_in[8];
    const float* Vr = (const float*)d_in[9];
    const float* Wo = (const float*)d_in[10];
    const float* bo = (const float*)d_in[11];
    float* out = (float*)d_out;

    const int scan_smem = (49152 + 3 * 1152) * (int)sizeof(float);
    cudaFuncSetAttribute(scan_kernel, cudaFuncAttributeMaxDynamicSharedMemorySize, scan_smem);

    dim3 pg(HH / 64, TT, 3);
    proj_kernel<<<pg, 256>>>(X, Wx, Uz, Ur, bx, bz, br);
    scan_kernel<<<NCTA, 256, scan_smem>>>(Wh, Vz, Vr);
    out_kernel<<<OUTD / 4, 256>>>(Wo, bo, out);
}

// round 15
// speedup vs baseline: 1.6205x; 1.2564x over previous
#include <cuda_runtime.h>
#include <cuda_bf16.h>
#include <math.h>

#define BB   64
#define TT   512
#define IND  256
#define HH   1024
#define OUTD 256

#define NCTA 64
#define COLS 16
#define RSTR 76

// -------- device scratch --------
__device__ float g_xh[TT * BB * HH];      // [t][j][b]
__device__ float g_xz[TT * BB * HH];
__device__ float g_xr[TT * BB * HH];
__device__ unsigned g_hB[2][32768];       // h  bf16x2-packed A-frags, double-buffered
__device__ float g_hrP[2][HH * BB];       // h*r tf32 fragment-packed, double-buffered
__device__ float g_hT [HH * BB];          // plain [j][b], final step only
__device__ unsigned g_fh [NCTA];
__device__ unsigned g_fhr[NCTA];

// -------- helpers --------
__device__ __forceinline__ unsigned cvt_tf32(float x) {
    unsigned r; asm("cvt.rna.tf32.f32 %0, %1;" : "=r"(r) : "f"(x)); return r;
}
__device__ __forceinline__ unsigned bf16pack(float hi, float lo) {
    unsigned r; asm("cvt.rn.bf16x2.f32 %0, %1, %2;" : "=r"(r) : "f"(hi), "f"(lo)); return r;
}
__device__ __forceinline__ void mma8(float (&d)[4], const unsigned (&a)[4], const unsigned (&b)[2]) {
    asm volatile("mma.sync.aligned.m16n8k8.row.col.f32.tf32.tf32.f32 "
                 "{%0,%1,%2,%3}, {%4,%5,%6,%7}, {%8,%9}, {%0,%1,%2,%3};"
                 : "+f"(d[0]), "+f"(d[1]), "+f"(d[2]), "+f"(d[3])
                 : "r"(a[0]), "r"(a[1]), "r"(a[2]), "r"(a[3]), "r"(b[0]), "r"(b[1]));
}
__device__ __forceinline__ void mma16(float (&d)[4], const unsigned (&a)[4], const unsigned (&b)[2]) {
    asm volatile("mma.sync.aligned.m16n8k16.row.col.f32.bf16.bf16.f32 "
                 "{%0,%1,%2,%3}, {%4,%5,%6,%7}, {%8,%9}, {%0,%1,%2,%3};"
                 : "+f"(d[0]), "+f"(d[1]), "+f"(d[2]), "+f"(d[3])
                 : "r"(a[0]), "r"(a[1]), "r"(a[2]), "r"(a[3]), "r"(b[0]), "r"(b[1]));
}
__device__ __forceinline__ float sigm_(float x) { return 1.0f / (1.0f + __expf(-x)); }

__device__ __forceinline__ unsigned long long splat2(float x) {
    unsigned long long r; asm("mov.b64 %0, {%1, %1};" : "=l"(r) : "f"(x)); return r;
}
__device__ __forceinline__ unsigned long long pack2(float x, float y) {
    unsigned long long r; asm("mov.b64 %0, {%1, %2};" : "=l"(r) : "f"(x), "f"(y)); return r;
}
__device__ __forceinline__ void fma2(unsigned long long& d, unsigned long long a, unsigned long long b) {
    asm("fma.rn.f32x2 %0, %1, %2, %0;" : "+l"(d) : "l"(a), "l"(b));
}
__device__ __forceinline__ float2 unpack2(unsigned long long v) {
    float2 f; asm("mov.b64 {%0, %1}, %2;" : "=f"(f.x), "=f"(f.y) : "l"(v)); return f;
}

// -------- dataflow sync --------
__device__ __forceinline__ void publish(unsigned* flag, unsigned val) {
    asm volatile("st.release.gpu.global.u32 [%0], %1;" :: "l"(flag), "r"(val) : "memory");
}
// Warp-collective wait on 8 producer CTAs (lanes poll flags[base + (lane&7)]).
__device__ __forceinline__ void wait8(const unsigned* flags, int base, unsigned target) {
    const unsigned* p = flags + base + (threadIdx.x & 7);
    unsigned v;
    do {
        asm volatile("ld.acquire.gpu.global.u32 %0, [%1];" : "=r"(v) : "l"(p) : "memory");
    } while (!__all_sync(0xffffffffu, (int)(v - target) >= 0));
}

// -------- kernel 1: input projections --------
__global__ __launch_bounds__(256) void proj_kernel(
    const float* __restrict__ X,
    const float* __restrict__ W0, const float* __restrict__ W1, const float* __restrict__ W2,
    const float* __restrict__ b0, const float* __restrict__ b1, const float* __restrict__ b2)
{
    __shared__ float As[32][68];
    __shared__ float Bs[32][68];

    const int z = blockIdx.z;
    const float* W    = (z == 0) ? W0 : (z == 1) ? W1 : W2;
    const float* bias = (z == 0) ? b0 : (z == 1) ? b1 : b2;
    float*       outp = (z == 0) ? g_xh : (z == 1) ? g_xz : g_xr;

    const int t   = blockIdx.y;
    const int j0  = blockIdx.x * 64;
    const int tid = threadIdx.x;
    const int ty  = tid >> 4;
    const int tx  = tid & 15;

    unsigned long long acc2[4][2];
#pragma unroll
    for (int i = 0; i < 4; i++) { acc2[i][0] = 0ull; acc2[i][1] = 0ull; }

    for (int kt = 0; kt < IND; kt += 32) {
#pragma unroll
        for (int l = 0; l < 8; l++) {
            int flat = tid + l * 256;
            int row = flat >> 5, col = flat & 31;
            As[col][row] = W[(j0 + row) * IND + kt + col];
            Bs[col][row] = X[row * (TT * IND) + t * IND + kt + col];
        }
        __syncthreads();
#pragma unroll
        for (int kk = 0; kk < 32; kk++) {
            float4 a4 = *reinterpret_cast<const float4*>(&As[kk][ty * 4]);
            float4 b4 = *reinterpret_cast<const float4*>(&Bs[kk][tx * 4]);
            unsigned long long p01 = pack2(b4.x, b4.y);
            unsigned long long p23 = pack2(b4.z, b4.w);
            float a[4] = { a4.x, a4.y, a4.z, a4.w };
#pragma unroll
            for (int i = 0; i < 4; i++) {
                unsigned long long aa = splat2(a[i]);
                fma2(acc2[i][0], aa, p01);
                fma2(acc2[i][1], aa, p23);
            }
        }
        __syncthreads();
    }
#pragma unroll
    for (int i = 0; i < 4; i++) {
        int j = j0 + ty * 4 + i;
        float bvv = bias[j];
        float2 p0 = unpack2(acc2[i][0]);
        float2 p1 = unpack2(acc2[i][1]);
        float4 v = make_float4(p0.x + bvv, p0.y + bvv, p1.x + bvv, p1.y + bvv);
        *reinterpret_cast<float4*>(&outp[t * (HH * BB) + j * BB + tx * 4]) = v;
    }
}

// -------- cross-warp reduction (R8 verbatim) --------
__device__ __forceinline__ void reduce16(float* red, const float (*a)[2][4],
                                         int w, int c, int q, int jj, int b0, float (&s)[4])
{
    if (w < 4) {
#pragma unroll
        for (int mt = 0; mt < 4; mt++)
#pragma unroll
            for (int nt = 0; nt < 2; nt++) {
                float* p = &red[(w * 16 + nt * 8 + 2 * c) * RSTR + mt * 16 + q];
                p[0] = a[mt][nt][0]; p[RSTR] = a[mt][nt][1];
                p[8] = a[mt][nt][2]; p[RSTR + 8] = a[mt][nt][3];
            }
    }
    __syncthreads();
    if (w >= 4) {
#pragma unroll
        for (int mt = 0; mt < 4; mt++)
#pragma unroll
            for (int nt = 0; nt < 2; nt++) {
                float* p = &red[((w - 4) * 16 + nt * 8 + 2 * c) * RSTR + mt * 16 + q];
                p[0] += a[mt][nt][0]; p[RSTR] += a[mt][nt][1];
                p[8] += a[mt][nt][2]; p[RSTR + 8] += a[mt][nt][3];
            }
    }
    __syncthreads();
    s[0] = s[1] = s[2] = s[3] = 0.f;
#pragma unroll
    for (int p4 = 0; p4 < 4; p4++) {
        float4 v = *(const float4*)&red[(p4 * 16 + jj) * RSTR + b0];
        s[0] += v.x; s[1] += v.y; s[2] += v.z; s[3] += v.w;
    }
}

// -------- kernel 2: persistent scan --------
// Phase 1: tf32 k8 (hr, precision path). Phase 2: bf16 k16 (gates, 2x MAC/instr).
__global__ __launch_bounds__(256, 1) void scan_kernel(
    const float* __restrict__ Wh, const float* __restrict__ Vz, const float* __restrict__ Vr)
{
    extern __shared__ float smem[];
    float*    Bp   = smem;                           // Wh tf32 frags: 16384 floats
    unsigned* Bz16 = (unsigned*)(smem + 16384);      // Vz bf16 frags: 8192 u32
    unsigned* Br16 = (unsigned*)(smem + 24576);      // Vr bf16 frags: 8192 u32
    float*    red  = smem + 32768;                   // 4*16*RSTR floats

    const int tid  = threadIdx.x;
    const int w    = tid >> 5;
    const int lane = tid & 31;
    const int j0   = blockIdx.x * COLS;

    const unsigned F0h  = g_fh [blockIdx.x];
    const unsigned F0hr = g_fhr[blockIdx.x];

    // Wh tf32 fragments (R8 packing, g=0 slice)
    for (int idx = tid; idx < COLS * HH; idx += 256) {
        int j = idx >> 10, k = idx & 1023;
        float v = Wh[(j0 + j) * HH + k];
        int ksg = k >> 3, kk = k & 7;
        Bp[((ksg * 2 + (j >> 3)) * 64) + ((j & 7) * 4 + (kk & 3)) * 2 + (kk >> 2)]
            = __uint_as_float(cvt_tf32(v));
    }
    // Vz/Vr bf16 fragments: slot((kc*2+nt)*32 + q*4+c)*2 + i  holds V[n][k],V[n][k+1]
    // with n = nt*8+q, k = kc*16 + 2c + 8i
    for (int idx = tid; idx < COLS * (HH / 2); idx += 256) {
        int k2 = idx & 511, jl = idx >> 9;
        int k = 2 * k2;
        int kc = k2 >> 3, k2o = k2 & 7;
        int cc = k2o & 3, ii = k2o >> 2;
        int qq = jl & 7, nt = jl >> 3;
        int ad = ((kc * 2 + nt) * 32 + qq * 4 + cc) * 2 + ii;
        const float* Vz_r = &Vz[(j0 + jl) * HH + k];
        const float* Vr_r = &Vr[(j0 + jl) * HH + k];
        Bz16[ad] = bf16pack(Vz_r[1], Vz_r[0]);
        Br16[ad] = bf16pack(Vr_r[1], Vr_r[0]);
    }

    const int jj = tid >> 4;
    const int b0 = (tid & 15) * 4;
    const int kj = j0 + jj;
    const int pkk = kj & 7;
    const int pbi = b0 & 15;
    const int pbase = (((kj >> 7) * 4 + (b0 >> 4)) * 16 + ((kj >> 3) & 15)) * 128
                    + ((pbi & 7) * 4 + (pkk & 3)) * 4 + ((pbi >> 3) + 2 * (pkk >> 2));

    // bf16 h store addressing (even-jj threads store pairs (jj, jj+1))
    const int cc_h = (jj >> 1) & 3;
    const int nt_h = jj >> 3;
    const int mt_h = b0 >> 4;
    const int p_h  = (b0 >> 3) & 1;
    const int q0_h = b0 & 7;
    const int hb_base = ((blockIdx.x * 4 + mt_h) * 32 + q0_h * 4 + cc_h) * 4 + p_h + 2 * nt_h;

    float hst[4] = {0, 0, 0, 0}, zst[4] = {0, 0, 0, 0};

    // hr@-1 = 0 into buffer 1, publish
#pragma unroll
    for (int i = 0; i < 4; i++) __stcg(&g_hrP[1][pbase + i * 16], 0.0f);
    __syncthreads();
    if (tid == 0) publish(&g_fhr[blockIdx.x], F0hr + 1);

    const int c = lane & 3, q = lane >> 2;
    const int Abase = lane * 4;
    const int prodbase = w * 8;      // 8 producer CTAs of this warp's K=128

    for (int t = 0; t < TT; t++) {
        const int xo = t * (HH * BB) + kj * BB + b0;
        float4 xh4 = *(const float4*)&g_xh[xo];
        float4 xz4 = *(const float4*)&g_xz[xo];
        float4 xr4 = *(const float4*)&g_xr[xo];

        // ---------- phase 1: (h*r) @ Wh^T  (tf32 k8) ----------
        wait8(g_fhr, prodbase, F0hr + 1 + t);
        const float* hrbuf = g_hrP[(t + 1) & 1];

        float acc[4][2][4];
#pragma unroll
        for (int mt = 0; mt < 4; mt++)
#pragma unroll
            for (int nt = 0; nt < 2; nt++)
#pragma unroll
                for (int r = 0; r < 4; r++) acc[mt][nt][r] = 0.f;

#pragma unroll 4
        for (int ks = 0; ks < 16; ks++) {
            int kg = w * 16 + ks;
            float2 f0 = *(const float2*)&Bp[(kg * 2 + 0) * 64 + lane * 2];
            float2 f1 = *(const float2*)&Bp[(kg * 2 + 1) * 64 + lane * 2];
            unsigned bq0[2] = { __float_as_uint(f0.x), __float_as_uint(f0.y) };
            unsigned bq1[2] = { __float_as_uint(f1.x), __float_as_uint(f1.y) };
#pragma unroll
            for (int mt = 0; mt < 4; mt++) {
                float4 av = __ldcg((const float4*)&hrbuf[((w * 4 + mt) * 16 + ks) * 128 + Abase]);
                unsigned af[4] = { __float_as_uint(av.x), __float_as_uint(av.y),
                                   __float_as_uint(av.z), __float_as_uint(av.w) };
                mma8(acc[mt][0], af, bq0);
                mma8(acc[mt][1], af, bq1);
            }
        }
        {
            float s[4];
            reduce16(red, acc, w, c, q, jj, b0, s);
            float xv[4] = { xh4.x, xh4.y, xh4.z, xh4.w };
#pragma unroll
            for (int i = 0; i < 4; i++) {
                float ht = tanhf(xv[i] + s[i]);
                hst[i] = zst[i] * hst[i] + (1.f - zst[i]) * ht;
            }
            // bf16x2 exchange: pair (jj, jj+1) via shfl, even-jj threads store
            unsigned* hb = g_hB[t & 1];
#pragma unroll
            for (int i = 0; i < 4; i++) {
                float ph = __shfl_xor_sync(0xffffffffu, hst[i], 16);
                if ((tid & 16) == 0)
                    __stcg(&hb[hb_base + i * 16], bf16pack(ph, hst[i]));
            }
            if (t == TT - 1) {
#pragma unroll
                for (int i = 0; i < 4; i++) g_hT[kj * BB + b0 + i] = hst[i];
            }
        }
        __syncthreads();
        if (tid == 0) publish(&g_fh[blockIdx.x], F0h + 1 + t);

        // ---------- phase 2: h @ Vz^T and h @ Vr^T  (bf16 k16) ----------
        wait8(g_fh, prodbase, F0h + 1 + t);
        const unsigned* hbc = g_hB[t & 1];

        float az[4][2][4], ar[4][2][4];
#pragma unroll
        for (int mt = 0; mt < 4; mt++)
#pragma unroll
            for (int nt = 0; nt < 2; nt++)
#pragma unroll
                for (int r = 0; r < 4; r++) { az[mt][nt][r] = 0.f; ar[mt][nt][r] = 0.f; }

#pragma unroll 4
        for (int kc8 = 0; kc8 < 8; kc8++) {
            int kcg = w * 8 + kc8;
            uint2 bz0 = *(const uint2*)&Bz16[((kcg * 2 + 0) * 32 + lane) * 2];
            uint2 bz1 = *(const uint2*)&Bz16[((kcg * 2 + 1) * 32 + lane) * 2];
            uint2 br0 = *(const uint2*)&Br16[((kcg * 2 + 0) * 32 + lane) * 2];
            uint2 br1 = *(const uint2*)&Br16[((kcg * 2 + 1) * 32 + lane) * 2];
            unsigned vz0[2] = { bz0.x, bz0.y }, vz1[2] = { bz1.x, bz1.y };
            unsigned vr0[2] = { br0.x, br0.y }, vr1[2] = { br1.x, br1.y };
#pragma unroll
            for (int mt = 0; mt < 4; mt++) {
                uint4 av = __ldcg((const uint4*)&hbc[((kcg * 4 + mt) * 32 + lane) * 4]);
                unsigned af[4] = { av.x, av.y, av.z, av.w };
                mma16(az[mt][0], af, vz0);
                mma16(az[mt][1], af, vz1);
                mma16(ar[mt][0], af, vr0);
                mma16(ar[mt][1], af, vr1);
            }
        }
        {
            float sz[4], sr[4];
            reduce16(red, az, w, c, q, jj, b0, sz);
            __syncthreads();
            reduce16(red, ar, w, c, q, jj, b0, sr);
            float zv[4] = { xz4.x, xz4.y, xz4.z, xz4.w };
            float rv[4] = { xr4.x, xr4.y, xr4.z, xr4.w };
            float* hrw = g_hrP[t & 1];
#pragma unroll
            for (int i = 0; i < 4; i++) {
                zst[i] = sigm_(zv[i] + sz[i]);
                float ri = sigm_(rv[i] + sr[i]);
                __stcg(&hrw[pbase + i * 16], __uint_as_float(cvt_tf32(hst[i] * ri)));
            }
        }
        __syncthreads();
        if (tid == 0) publish(&g_fhr[blockIdx.x], F0hr + 2 + t);
    }
}

// -------- kernel 3: output projection --------
__global__ __launch_bounds__(256) void out_kernel(
    const float* __restrict__ Wo, const float* __restrict__ bo, float* __restrict__ out)
{
    const int b = threadIdx.x & 63;
    const int o = blockIdx.x * 4 + (threadIdx.x >> 6);
    float s = 0.f;
#pragma unroll 8
    for (int j = 0; j < HH; j++)
        s += g_hT[j * BB + b] * Wo[o * HH + j];
    out[b * OUTD + o] = s + bo[o];
}

extern "C" void kernel_launch(void* const* d_in, const int* in_sizes, int n_in,
                              void* d_out, int out_size) {
    const float* X  = (const float*)d_in[0];
    const float* Wx = (const float*)d_in[1];
    const float* bx = (const float*)d_in[2];
    const float* Wh = (const float*)d_in[3];
    const float* Uz = (const float*)d_in[4];
    const float* bz = (const float*)d_in[5];
    const float* Vz = (const float*)d_in[6];
    const float* Ur = (const float*)d_in[7];
    const float* br = (const float*)d_in[8];
    const float* Vr = (const float*)d_in[9];
    const float* Wo = (const float*)d_in[10];
    const float* bo = (const float*)d_in[11];
    float* out = (float*)d_out;

    const int scan_smem = (32768 + 4 * 16 * RSTR) * (int)sizeof(float);
    cudaFuncSetAttribute(scan_kernel, cudaFuncAttributeMaxDynamicSharedMemorySize, scan_smem);

    dim3 pg(HH / 64, TT, 3);
    proj_kernel<<<pg, 256>>>(X, Wx, Uz, Ur, bx, bz, br);
    scan_kernel<<<NCTA, 256, scan_smem>>>(Wh, Vz, Vr);
    out_kernel<<<OUTD / 4, 256>>>(Wo, bo, out);
}